// round 15
// baseline (speedup 1.0000x reference)
#include <cuda_runtime.h>
#include <cstdint>

#define ROW_LEN 2048
#define NTHREADS 256
#define NWARP 8
#define K_TOP 64
#define NBINS 512            // bins 1..511 cover x in [1.0, 5.0); bin 0 unused (catch-all derived)
#define FSCALE 128.0f
#define FBIAS  -127.0f
#define FULLMASK 0xffffffffu

typedef unsigned long long u64;

// ---- packed f32x2 helpers (sm_103a) ----
__device__ __forceinline__ u64 pack2(float lo, float hi) {
    u64 r;
    asm("mov.b64 %0, {%1, %2};" : "=l"(r) : "f"(lo), "f"(hi));
    return r;
}
__device__ __forceinline__ float2 unpack2(u64 p) {
    float2 r;
    asm("mov.b64 {%0, %1}, %2;" : "=f"(r.x), "=f"(r.y) : "l"(p));
    return r;
}
__device__ __forceinline__ u64 fma2(u64 a, u64 b, u64 c) {
    u64 d;
    asm("fma.rn.f32x2 %0, %1, %2, %3;" : "=l"(d) : "l"(a), "l"(b), "l"(c));
    return d;
}
__device__ __forceinline__ u64 mul2(u64 a, u64 b) {
    u64 d;
    asm("mul.rn.f32x2 %0, %1, %2;" : "=l"(d) : "l"(a), "l"(b));
    return d;
}
__device__ __forceinline__ float ex2a(float x) {
    float r;
    asm("ex2.approx.f32 %0, %1;" : "=f"(r) : "f"(x));
    return r;
}

__global__ __launch_bounds__(NTHREADS, 8)   // cap regs at 32 -> 8 CTAs/SM
void topk_softmax_kernel(const float* __restrict__ in, float* __restrict__ out) {
    const int tid  = threadIdx.x;
    const int lane = tid & 31;
    const int wid  = tid >> 5;
    const size_t rbase = (size_t)blockIdx.x * ROW_LEN;

    const float4* rp4 = reinterpret_cast<const float4*>(in + rbase);
    float4*       op4 = reinterpret_cast<float4*>(out + rbase);

    __shared__ int   hist[NBINS];
    __shared__ int   binmax[NBINS];      // int bits of per-bin max (members >= 1.0 > 0)
    __shared__ int   binmin[NBINS];      // int bits of per-bin min
    __shared__ float cand[ROW_LEN];      // fallback-only candidate buffer
    __shared__ int   s_wsum[NWARP];
    __shared__ int   s_bin, s_kc, s_cnt, s_mode;
    __shared__ float s_vk, s_sum;

    // ---- 1. Issue loads; init scratch while they're in flight ----
    float4 a = rp4[tid];
    float4 b = rp4[tid + NTHREADS];
    reinterpret_cast<int2*>(hist)[tid]   = make_int2(0, 0);
    reinterpret_cast<int2*>(binmax)[tid] = make_int2(0, 0);
    reinterpret_cast<int2*>(binmin)[tid] = make_int2(0x7f800000, 0x7f800000);
    if (tid == 0) { s_cnt = 0; s_sum = 0.0f; }

    float2 v2[4];
    v2[0] = make_float2(a.x, a.y); v2[1] = make_float2(a.z, a.w);
    v2[2] = make_float2(b.x, b.y); v2[3] = make_float2(b.z, b.w);
    __syncthreads();                                          // B1

    // ---- 2. Conditional tail histogram + per-bin max/min (fused vk resolution) ----
    {
        const u64 SC = pack2(FSCALE, FSCALE);
        const u64 BI = pack2(FBIAS, FBIAS);
        #pragma unroll
        for (int j = 0; j < 4; j++) {
            float2 f = unpack2(fma2(pack2(v2[j].x, v2[j].y), SC, BI));
            if (f.x >= 1.0f) {
                int bi = min((int)f.x, NBINS - 1);
                int bits = __float_as_int(v2[j].x);
                atomicAdd(&hist[bi], 1);
                atomicMax(&binmax[bi], bits);
                atomicMin(&binmin[bi], bits);
            }
            if (f.y >= 1.0f) {
                int bi = min((int)f.y, NBINS - 1);
                int bits = __float_as_int(v2[j].y);
                atomicAdd(&hist[bi], 1);
                atomicMax(&binmax[bi], bits);
                atomicMin(&binmin[bi], bits);
            }
        }
    }
    __syncthreads();                                          // B2

    // ---- 3. Distributed suffix scan; thread t owns bins (2t, 2t+1) ----
    const int2 h = reinterpret_cast<int2*>(hist)[tid];
    const int lsum = h.x + h.y;
    int s = lsum;                                 // warp suffix incl. self
    #pragma unroll
    for (int o = 1; o < 32; o <<= 1) {
        int t = __shfl_down_sync(FULLMASK, s, o);
        if (lane + o < 32) s += t;
    }
    if (lane == 0) s_wsum[wid] = s;
    __syncthreads();                                          // B3

    int T = s - lsum;                             // count in bins strictly above my pair
    #pragma unroll
    for (int w = 1; w < NWARP; w++)
        if (w > wid) T += s_wsum[w];

    if (T < K_TOP && T + lsum >= K_TOP) {         // unique thread owns the crossing
        int bin, kc, hcnt;
        const int nsuf = T + h.y;                 // bin 2t+1 is the higher bin
        if (nsuf >= K_TOP) { bin = tid * 2 + 1; kc = K_TOP - T;    hcnt = h.y; }
        else               { bin = tid * 2;     kc = K_TOP - nsuf; hcnt = h.x; }
        s_bin = bin;
        s_kc  = kc;
        if (kc == 1)         { s_vk = __int_as_float(binmax[bin]); s_mode = 1; }
        else if (kc == hcnt) { s_vk = __int_as_float(binmin[bin]); s_mode = 1; }
        else                 { s_mode = 0; }                       // rare fallback
    }
    if (tid == 0) {                               // catch-all: threshold below range
        const int total = T + lsum;               // thread 0's suffix = all histed elems
        if (total < K_TOP) {
            s_bin  = 0;
            s_kc   = K_TOP - total;
            s_mode = 0;
        }
    }
    __syncthreads();                                          // B4

    // ---- 4. Rare fallback: compact crossing bin + exact select ----
    if (s_mode == 0) {                            // block-uniform branch
        const int bstar = s_bin;
        const float flo = (bstar == 0)         ? -__int_as_float(0x7f800000) : (float)bstar;
        const float fhi = (bstar == NBINS - 1) ?  __int_as_float(0x7f800000) : (float)(bstar + 1);
        const u64 SC = pack2(FSCALE, FSCALE);
        const u64 BI = pack2(FBIAS, FBIAS);
        #pragma unroll
        for (int j = 0; j < 4; j++) {
            float2 f = unpack2(fma2(pack2(v2[j].x, v2[j].y), SC, BI));
            if (f.x >= flo && f.x < fhi) { int i0 = atomicAdd(&s_cnt, 1); cand[i0] = v2[j].x; }
            if (f.y >= flo && f.y < fhi) { int i1 = atomicAdd(&s_cnt, 1); cand[i1] = v2[j].y; }
        }
        __syncthreads();                                      // B5a (rare)
        if (wid == 0) {
            const int c  = s_cnt;
            int   remaining = s_kc;
            float bound = __int_as_float(0x7f800000);
            float vk;
            for (;;) {
                float m = -__int_as_float(0x7f800000);
                for (int i = lane; i < c; i += 32) {
                    float x = cand[i];
                    if (x < bound) m = fmaxf(m, x);
                }
                #pragma unroll
                for (int o = 16; o; o >>= 1) m = fmaxf(m, __shfl_xor_sync(FULLMASK, m, o));
                int cnt = 0;
                for (int i = lane; i < c; i += 32) cnt += (cand[i] == m);
                #pragma unroll
                for (int o = 16; o; o >>= 1) cnt += __shfl_xor_sync(FULLMASK, cnt, o);
                if (cnt >= remaining) { vk = m; break; }
                remaining -= cnt;
                bound = m;
            }
            if (lane == 0) s_vk = vk;
        }
        __syncthreads();                                      // B5b (rare)
    }

    const float vk = s_vk;

    // ---- 5. Masked exp + sum: e = ex2(fma(v, log2e, -vk*log2e)), mask on v>=vk ----
    float sum;
    {
        const float L2E = 1.4426950408889634f;
        const u64 L2 = pack2(L2E, L2E);
        const float nc = -vk * L2E;
        const u64 NC = pack2(nc, nc);
        sum = 0.0f;
        #pragma unroll
        for (int j = 0; j < 4; j++) {
            float2 t = unpack2(fma2(pack2(v2[j].x, v2[j].y), L2, NC));
            float e0 = ex2a(t.x);
            float e1 = ex2a(t.y);
            e0 = (v2[j].x >= vk) ? e0 : 0.0f;
            e1 = (v2[j].y >= vk) ? e1 : 0.0f;
            v2[j].x = e0; v2[j].y = e1;
            sum += e0 + e1;
        }
    }
    #pragma unroll
    for (int o = 16; o; o >>= 1) sum += __shfl_xor_sync(FULLMASK, sum, o);
    if (lane == 0) atomicAdd(&s_sum, sum);
    __syncthreads();                                          // B5

    const float inv = __fdividef(1.0f, s_sum);

    // ---- 6. Scale (packed) + store (coalesced float4) ----
    const u64 IV = pack2(inv, inv);
    float2 o0 = unpack2(mul2(pack2(v2[0].x, v2[0].y), IV));
    float2 o1 = unpack2(mul2(pack2(v2[1].x, v2[1].y), IV));
    float2 o2 = unpack2(mul2(pack2(v2[2].x, v2[2].y), IV));
    float2 o3 = unpack2(mul2(pack2(v2[3].x, v2[3].y), IV));
    op4[tid]            = make_float4(o0.x, o0.y, o1.x, o1.y);
    op4[tid + NTHREADS] = make_float4(o2.x, o2.y, o3.x, o3.y);
}

extern "C" void kernel_launch(void* const* d_in, const int* in_sizes, int n_in,
                              void* d_out, int out_size) {
    const float* in  = (const float*)d_in[0];
    float*       out = (float*)d_out;
    const int nrows = in_sizes[0] / ROW_LEN;   // 2*16*2048 = 65536
    topk_softmax_kernel<<<nrows, NTHREADS>>>(in, out);
}

// round 16
// speedup vs baseline: 1.0370x; 1.0370x over previous
#include <cuda_runtime.h>
#include <cstdint>

#define ROW_LEN 2048
#define NTHREADS 256
#define NWARP 8
#define K_TOP 64
#define NBINS 256            // bins 1..255 cover x in [1.5, ~3.49); bin 255 clamps above;
                             // bin 0 = derived catch-all for x < 1.5
#define FSCALE 128.0f
#define FBIAS  -191.0f       // f = 128*x - 191; x=1.5 -> f=1.0
#define FULLMASK 0xffffffffu

typedef unsigned long long u64;

// ---- packed f32x2 helpers (sm_103a) ----
__device__ __forceinline__ u64 pack2(float lo, float hi) {
    u64 r;
    asm("mov.b64 %0, {%1, %2};" : "=l"(r) : "f"(lo), "f"(hi));
    return r;
}
__device__ __forceinline__ float2 unpack2(u64 p) {
    float2 r;
    asm("mov.b64 {%0, %1}, %2;" : "=f"(r.x), "=f"(r.y) : "l"(p));
    return r;
}
__device__ __forceinline__ u64 fma2(u64 a, u64 b, u64 c) {
    u64 d;
    asm("fma.rn.f32x2 %0, %1, %2, %3;" : "=l"(d) : "l"(a), "l"(b), "l"(c));
    return d;
}
__device__ __forceinline__ u64 mul2(u64 a, u64 b) {
    u64 d;
    asm("mul.rn.f32x2 %0, %1, %2;" : "=l"(d) : "l"(a), "l"(b));
    return d;
}
__device__ __forceinline__ float ex2a(float x) {
    float r;
    asm("ex2.approx.f32 %0, %1;" : "=f"(r) : "f"(x));
    return r;
}

__global__ __launch_bounds__(NTHREADS, 8)   // cap regs at 32 -> 8 CTAs/SM
void topk_softmax_kernel(const float* __restrict__ in, float* __restrict__ out) {
    const int tid  = threadIdx.x;
    const int lane = tid & 31;
    const int wid  = tid >> 5;
    const size_t rbase = (size_t)blockIdx.x * ROW_LEN;

    const float4* rp4 = reinterpret_cast<const float4*>(in + rbase);
    float4*       op4 = reinterpret_cast<float4*>(out + rbase);

    __shared__ int   hist[NBINS];
    __shared__ int   binmax[NBINS];      // int bits of per-bin max (members >= 1.5 > 0)
    __shared__ int   binmin[NBINS];      // int bits of per-bin min
    __shared__ float cand[ROW_LEN];      // fallback-only candidate buffer
    __shared__ int   s_wsum[NWARP];
    __shared__ int   s_bin, s_kc, s_cnt, s_mode;
    __shared__ float s_vk, s_sum;

    // ---- 1. Issue loads; init scratch while they're in flight ----
    float4 a = rp4[tid];
    float4 b = rp4[tid + NTHREADS];
    hist[tid]   = 0;
    binmax[tid] = 0;
    binmin[tid] = 0x7f800000;
    if (tid == 0) { s_cnt = 0; s_sum = 0.0f; }

    float2 v2[4];
    v2[0] = make_float2(a.x, a.y); v2[1] = make_float2(a.z, a.w);
    v2[2] = make_float2(b.x, b.y); v2[3] = make_float2(b.z, b.w);
    __syncthreads();                                          // B1

    // ---- 2. Conditional tail histogram + per-bin max/min (~6.7% of elems) ----
    {
        const u64 SC = pack2(FSCALE, FSCALE);
        const u64 BI = pack2(FBIAS, FBIAS);
        #pragma unroll
        for (int j = 0; j < 4; j++) {
            float2 f = unpack2(fma2(pack2(v2[j].x, v2[j].y), SC, BI));
            if (f.x >= 1.0f) {
                int bi = min((int)f.x, NBINS - 1);
                int bits = __float_as_int(v2[j].x);
                atomicAdd(&hist[bi], 1);
                atomicMax(&binmax[bi], bits);
                atomicMin(&binmin[bi], bits);
            }
            if (f.y >= 1.0f) {
                int bi = min((int)f.y, NBINS - 1);
                int bits = __float_as_int(v2[j].y);
                atomicAdd(&hist[bi], 1);
                atomicMax(&binmax[bi], bits);
                atomicMin(&binmin[bi], bits);
            }
        }
    }
    __syncthreads();                                          // B2

    // ---- 3. Suffix scan, 1 bin/thread; locate crossing + resolve vk ----
    const int h = hist[tid];
    int s = h;                                    // warp suffix incl. self
    #pragma unroll
    for (int o = 1; o < 32; o <<= 1) {
        int t = __shfl_down_sync(FULLMASK, s, o);
        if (lane + o < 32) s += t;
    }
    if (lane == 0) s_wsum[wid] = s;
    __syncthreads();                                          // B3

    int S = s;                                    // suffix over bins >= tid
    #pragma unroll
    for (int w = 1; w < NWARP; w++)
        if (w > wid) S += s_wsum[w];
    const int Sn = S - h;

    if (S >= K_TOP && Sn < K_TOP) {               // unique crossing thread
        const int kc = K_TOP - Sn;                // rank within bin, from the top
        s_bin = tid;
        s_kc  = kc;
        if (kc == 1)      { s_vk = __int_as_float(binmax[tid]); s_mode = 1; }
        else if (kc == h) { s_vk = __int_as_float(binmin[tid]); s_mode = 1; }
        else              { s_mode = 0; }                        // rare fallback
    }
    if (tid == 0 && S < K_TOP) {                  // catch-all: threshold below range
        s_bin  = 0;
        s_kc   = K_TOP - S;                       // thread 0's suffix = total tail count
        s_mode = 0;
    }
    __syncthreads();                                          // B4

    // ---- 4. Rare fallback: compact crossing bin + exact select ----
    if (s_mode == 0) {                            // block-uniform branch
        const int bstar = s_bin;
        const float flo = (bstar == 0)         ? -__int_as_float(0x7f800000) : (float)bstar;
        const float fhi = (bstar == NBINS - 1) ?  __int_as_float(0x7f800000) : (float)(bstar + 1);
        const u64 SC = pack2(FSCALE, FSCALE);
        const u64 BI = pack2(FBIAS, FBIAS);
        #pragma unroll
        for (int j = 0; j < 4; j++) {
            float2 f = unpack2(fma2(pack2(v2[j].x, v2[j].y), SC, BI));
            if (f.x >= flo && f.x < fhi) { int i0 = atomicAdd(&s_cnt, 1); cand[i0] = v2[j].x; }
            if (f.y >= flo && f.y < fhi) { int i1 = atomicAdd(&s_cnt, 1); cand[i1] = v2[j].y; }
        }
        __syncthreads();                                      // (rare)
        if (wid == 0) {
            const int c  = s_cnt;
            int   remaining = s_kc;
            float bound = __int_as_float(0x7f800000);
            float vk;
            for (;;) {
                float m = -__int_as_float(0x7f800000);
                for (int i = lane; i < c; i += 32) {
                    float x = cand[i];
                    if (x < bound) m = fmaxf(m, x);
                }
                #pragma unroll
                for (int o = 16; o; o >>= 1) m = fmaxf(m, __shfl_xor_sync(FULLMASK, m, o));
                int cnt = 0;
                for (int i = lane; i < c; i += 32) cnt += (cand[i] == m);
                #pragma unroll
                for (int o = 16; o; o >>= 1) cnt += __shfl_xor_sync(FULLMASK, cnt, o);
                if (cnt >= remaining) { vk = m; break; }
                remaining -= cnt;
                bound = m;
            }
            if (lane == 0) s_vk = vk;
        }
        __syncthreads();                                      // (rare)
    }

    const float vk = s_vk;

    // ---- 5. Masked exp + sum: e = ex2(fma(v, log2e, -vk*log2e)), mask on v>=vk ----
    float sum;
    {
        const float L2E = 1.4426950408889634f;
        const u64 L2 = pack2(L2E, L2E);
        const float nc = -vk * L2E;
        const u64 NC = pack2(nc, nc);
        sum = 0.0f;
        #pragma unroll
        for (int j = 0; j < 4; j++) {
            float2 t = unpack2(fma2(pack2(v2[j].x, v2[j].y), L2, NC));
            float e0 = ex2a(t.x);
            float e1 = ex2a(t.y);
            e0 = (v2[j].x >= vk) ? e0 : 0.0f;
            e1 = (v2[j].y >= vk) ? e1 : 0.0f;
            v2[j].x = e0; v2[j].y = e1;
            sum += e0 + e1;
        }
    }
    #pragma unroll
    for (int o = 16; o; o >>= 1) sum += __shfl_xor_sync(FULLMASK, sum, o);
    if (lane == 0) atomicAdd(&s_sum, sum);
    __syncthreads();                                          // B5

    const float inv = __fdividef(1.0f, s_sum);

    // ---- 6. Scale (packed) + store (coalesced float4) ----
    const u64 IV = pack2(inv, inv);
    float2 o0 = unpack2(mul2(pack2(v2[0].x, v2[0].y), IV));
    float2 o1 = unpack2(mul2(pack2(v2[1].x, v2[1].y), IV));
    float2 o2 = unpack2(mul2(pack2(v2[2].x, v2[2].y), IV));
    float2 o3 = unpack2(mul2(pack2(v2[3].x, v2[3].y), IV));
    op4[tid]            = make_float4(o0.x, o0.y, o1.x, o1.y);
    op4[tid + NTHREADS] = make_float4(o2.x, o2.y, o3.x, o3.y);
}

extern "C" void kernel_launch(void* const* d_in, const int* in_sizes, int n_in,
                              void* d_out, int out_size) {
    const float* in  = (const float*)d_in[0];
    float*       out = (float*)d_out;
    const int nrows = in_sizes[0] / ROW_LEN;   // 2*16*2048 = 65536
    topk_softmax_kernel<<<nrows, NTHREADS>>>(in, out);
}

// round 17
// speedup vs baseline: 1.0766x; 1.0382x over previous
#include <cuda_runtime.h>
#include <cstdint>

#define ROW_LEN 2048
#define NTHREADS 256
#define NWARP 8
#define K_TOP 64
#define NBINS 512            // bins 1..511 cover x in [1.6, ~2.597); bin 511 clamps above;
                             // bin 0 = derived catch-all for x < 1.6
#define FSCALE 512.0f
#define FBIAS  -818.2f       // f = 512*x - 818.2; x=1.6 -> f=1.0
#define FULLMASK 0xffffffffu

typedef unsigned long long u64;

// ---- packed f32x2 helpers (sm_103a) ----
__device__ __forceinline__ u64 pack2(float lo, float hi) {
    u64 r;
    asm("mov.b64 %0, {%1, %2};" : "=l"(r) : "f"(lo), "f"(hi));
    return r;
}
__device__ __forceinline__ float2 unpack2(u64 p) {
    float2 r;
    asm("mov.b64 {%0, %1}, %2;" : "=f"(r.x), "=f"(r.y) : "l"(p));
    return r;
}
__device__ __forceinline__ u64 fma2(u64 a, u64 b, u64 c) {
    u64 d;
    asm("fma.rn.f32x2 %0, %1, %2, %3;" : "=l"(d) : "l"(a), "l"(b), "l"(c));
    return d;
}
__device__ __forceinline__ u64 mul2(u64 a, u64 b) {
    u64 d;
    asm("mul.rn.f32x2 %0, %1, %2;" : "=l"(d) : "l"(a), "l"(b));
    return d;
}
__device__ __forceinline__ float ex2a(float x) {
    float r;
    asm("ex2.approx.f32 %0, %1;" : "=f"(r) : "f"(x));
    return r;
}

__global__ __launch_bounds__(NTHREADS, 8)   // cap regs at 32 -> 8 CTAs/SM
void topk_softmax_kernel(const float* __restrict__ in, float* __restrict__ out) {
    const int tid  = threadIdx.x;
    const int lane = tid & 31;
    const int wid  = tid >> 5;
    const size_t rbase = (size_t)blockIdx.x * ROW_LEN;

    const float4* rp4 = reinterpret_cast<const float4*>(in + rbase);
    float4*       op4 = reinterpret_cast<float4*>(out + rbase);

    __shared__ int   hist[NBINS];
    __shared__ int   binmax[NBINS];      // int bits of per-bin max (members >= 1.6 > 0)
    __shared__ int   binmin[NBINS];      // int bits of per-bin min
    __shared__ float cand[ROW_LEN];      // fallback-only candidate buffer
    __shared__ int   s_wsum[NWARP];
    __shared__ int   s_bin, s_kc, s_cnt, s_mode;
    __shared__ float s_vk, s_sum;

    // ---- 1. Issue loads; init scratch while they're in flight ----
    float4 a = rp4[tid];
    float4 b = rp4[tid + NTHREADS];
    reinterpret_cast<int2*>(hist)[tid]   = make_int2(0, 0);
    reinterpret_cast<int2*>(binmax)[tid] = make_int2(0, 0);
    reinterpret_cast<int2*>(binmin)[tid] = make_int2(0x7f800000, 0x7f800000);
    if (tid == 0) { s_cnt = 0; s_sum = 0.0f; }

    float2 v2[4];
    v2[0] = make_float2(a.x, a.y); v2[1] = make_float2(a.z, a.w);
    v2[2] = make_float2(b.x, b.y); v2[3] = make_float2(b.z, b.w);
    __syncthreads();                                          // B1

    // ---- 2. Conditional tail histogram + per-bin max/min (~5.5% of elems) ----
    {
        const u64 SC = pack2(FSCALE, FSCALE);
        const u64 BI = pack2(FBIAS, FBIAS);
        #pragma unroll
        for (int j = 0; j < 4; j++) {
            float2 f = unpack2(fma2(pack2(v2[j].x, v2[j].y), SC, BI));
            if (f.x >= 1.0f) {
                int bi = min((int)f.x, NBINS - 1);
                int bits = __float_as_int(v2[j].x);
                atomicAdd(&hist[bi], 1);
                atomicMax(&binmax[bi], bits);
                atomicMin(&binmin[bi], bits);
            }
            if (f.y >= 1.0f) {
                int bi = min((int)f.y, NBINS - 1);
                int bits = __float_as_int(v2[j].y);
                atomicAdd(&hist[bi], 1);
                atomicMax(&binmax[bi], bits);
                atomicMin(&binmin[bi], bits);
            }
        }
    }
    __syncthreads();                                          // B2

    // ---- 3. Suffix scan; thread t owns bins (2t, 2t+1); resolve vk inline ----
    const int2 h = reinterpret_cast<int2*>(hist)[tid];
    const int lsum = h.x + h.y;
    int s = lsum;                                 // warp suffix incl. self
    #pragma unroll
    for (int o = 1; o < 32; o <<= 1) {
        int t = __shfl_down_sync(FULLMASK, s, o);
        if (lane + o < 32) s += t;
    }
    if (lane == 0) s_wsum[wid] = s;
    __syncthreads();                                          // B3

    int T = s - lsum;                             // count in bins strictly above my pair
    #pragma unroll
    for (int w = 1; w < NWARP; w++)
        if (w > wid) T += s_wsum[w];

    if (T < K_TOP && T + lsum >= K_TOP) {         // unique thread owns the crossing
        int bin, kc, hcnt;
        const int nsuf = T + h.y;                 // bin 2t+1 is the higher bin
        if (nsuf >= K_TOP) { bin = tid * 2 + 1; kc = K_TOP - T;    hcnt = h.y; }
        else               { bin = tid * 2;     kc = K_TOP - nsuf; hcnt = h.x; }
        s_bin = bin;
        s_kc  = kc;
        if (kc == 1)         { s_vk = __int_as_float(binmax[bin]); s_mode = 1; }
        else if (kc == hcnt) { s_vk = __int_as_float(binmin[bin]); s_mode = 1; }
        else                 { s_mode = 0; }                       // rare fallback
    }
    if (tid == 0) {                               // catch-all: threshold below range
        const int total = T + lsum;               // thread 0's suffix = all histed elems
        if (total < K_TOP) {
            s_bin  = 0;
            s_kc   = K_TOP - total;
            s_mode = 0;
        }
    }
    __syncthreads();                                          // B4

    // ---- 4. Rare fallback: compact crossing bin + exact select ----
    if (s_mode == 0) {                            // block-uniform branch (~1% of rows)
        const int bstar = s_bin;
        const float flo = (bstar == 0)         ? -__int_as_float(0x7f800000) : (float)bstar;
        const float fhi = (bstar == NBINS - 1) ?  __int_as_float(0x7f800000) : (float)(bstar + 1);
        const u64 SC = pack2(FSCALE, FSCALE);
        const u64 BI = pack2(FBIAS, FBIAS);
        #pragma unroll
        for (int j = 0; j < 4; j++) {
            float2 f = unpack2(fma2(pack2(v2[j].x, v2[j].y), SC, BI));
            if (f.x >= flo && f.x < fhi) { int i0 = atomicAdd(&s_cnt, 1); cand[i0] = v2[j].x; }
            if (f.y >= flo && f.y < fhi) { int i1 = atomicAdd(&s_cnt, 1); cand[i1] = v2[j].y; }
        }
        __syncthreads();                                      // (rare)
        if (wid == 0) {
            const int c  = s_cnt;
            int   remaining = s_kc;
            float bound = __int_as_float(0x7f800000);
            float vk;
            for (;;) {
                float m = -__int_as_float(0x7f800000);
                for (int i = lane; i < c; i += 32) {
                    float x = cand[i];
                    if (x < bound) m = fmaxf(m, x);
                }
                #pragma unroll
                for (int o = 16; o; o >>= 1) m = fmaxf(m, __shfl_xor_sync(FULLMASK, m, o));
                int cnt = 0;
                for (int i = lane; i < c; i += 32) cnt += (cand[i] == m);
                #pragma unroll
                for (int o = 16; o; o >>= 1) cnt += __shfl_xor_sync(FULLMASK, cnt, o);
                if (cnt >= remaining) { vk = m; break; }
                remaining -= cnt;
                bound = m;
            }
            if (lane == 0) s_vk = vk;
        }
        __syncthreads();                                      // (rare)
    }

    const float vk = s_vk;

    // ---- 5. Masked exp + sum: e = ex2(fma(v, log2e, -vk*log2e)), mask on v>=vk ----
    float sum;
    {
        const float L2E = 1.4426950408889634f;
        const u64 L2 = pack2(L2E, L2E);
        const float nc = -vk * L2E;
        const u64 NC = pack2(nc, nc);
        sum = 0.0f;
        #pragma unroll
        for (int j = 0; j < 4; j++) {
            float2 t = unpack2(fma2(pack2(v2[j].x, v2[j].y), L2, NC));
            float e0 = ex2a(t.x);
            float e1 = ex2a(t.y);
            e0 = (v2[j].x >= vk) ? e0 : 0.0f;
            e1 = (v2[j].y >= vk) ? e1 : 0.0f;
            v2[j].x = e0; v2[j].y = e1;
            sum += e0 + e1;
        }
    }
    #pragma unroll
    for (int o = 16; o; o >>= 1) sum += __shfl_xor_sync(FULLMASK, sum, o);
    if (lane == 0) atomicAdd(&s_sum, sum);
    __syncthreads();                                          // B5

    const float inv = __fdividef(1.0f, s_sum);

    // ---- 6. Scale (packed) + store (coalesced float4) ----
    const u64 IV = pack2(inv, inv);
    float2 o0 = unpack2(mul2(pack2(v2[0].x, v2[0].y), IV));
    float2 o1 = unpack2(mul2(pack2(v2[1].x, v2[1].y), IV));
    float2 o2 = unpack2(mul2(pack2(v2[2].x, v2[2].y), IV));
    float2 o3 = unpack2(mul2(pack2(v2[3].x, v2[3].y), IV));
    op4[tid]            = make_float4(o0.x, o0.y, o1.x, o1.y);
    op4[tid + NTHREADS] = make_float4(o2.x, o2.y, o3.x, o3.y);
}

extern "C" void kernel_launch(void* const* d_in, const int* in_sizes, int n_in,
                              void* d_out, int out_size) {
    const float* in  = (const float*)d_in[0];
    float*       out = (float*)d_out;
    const int nrows = in_sizes[0] / ROW_LEN;   // 2*16*2048 = 65536
    topk_softmax_kernel<<<nrows, NTHREADS>>>(in, out);
}